// round 6
// baseline (speedup 1.0000x reference)
#include <cuda_runtime.h>
#include <cstdint>

// Fan-model nonlinear mixing:
//   out[b,x] = L + (L^2 - Q)/2
//   L = sum_p E[b,p]   * a[p,x]
//   Q = sum_p E[b,p]^2 * a[p,x]^2
// E: (224, 12)  A: (12, 512*512)  out: (224, 512*512), all fp32.
//
// R6: R4 structure (8 px/thread, monolithic 224-band loop, 256 blocks),
// but the E table {e,e,-e^2,-e^2} lives in the CONSTANT bank instead of
// shared memory. Warp-uniform const loads -> LDCU / uniform-register
// operands for the packed FMAs: removes the LDS stream from the vector
// path and (if FFMA2 takes UR sources) cuts per-instruction RF bank
// pressure from 3 distinct operand pairs to 2.

#define NPIX (512 * 512)
#define NP   12
#define NB   224

__constant__ float4 cE[NB * NP];          // 43008 B (< 64KB const bank)
__device__ float4 g_tbl[NB * NP];         // staging, written by prep kernel

__global__ void prep_kernel(const float* __restrict__ E)
{
    int i = blockIdx.x * blockDim.x + threadIdx.x;
    if (i < NB * NP) {
        float e = E[i];
        g_tbl[i] = make_float4(e, e, -e * e, -e * e);
    }
}

__global__ __launch_bounds__(128, 2) void fm_mix_kernel(
    const float* __restrict__ A,
    float* __restrict__ out)
{
    const int t = blockIdx.x * blockDim.x + threadIdx.x;  // 8-pixel group id
    // 256 blocks * 128 thr * 8 px = NPIX exactly, no bounds check

    // Load a[p] for 8 adjacent pixels (two LDG.128 per p), square once.
    unsigned long long a0[NP], a1[NP], a2[NP], a3[NP];
    unsigned long long s0[NP], s1[NP], s2[NP], s3[NP];
#pragma unroll
    for (int p = 0; p < NP; p++) {
        const ulonglong2* row = (const ulonglong2*)(A + (size_t)p * NPIX);
        const ulonglong2 v0 = row[2 * t];
        const ulonglong2 v1 = row[2 * t + 1];
        a0[p] = v0.x; a1[p] = v0.y; a2[p] = v1.x; a3[p] = v1.y;
        asm("mul.rn.f32x2 %0, %1, %2;" : "=l"(s0[p]) : "l"(v0.x), "l"(v0.x));
        asm("mul.rn.f32x2 %0, %1, %2;" : "=l"(s1[p]) : "l"(v0.y), "l"(v0.y));
        asm("mul.rn.f32x2 %0, %1, %2;" : "=l"(s2[p]) : "l"(v1.x), "l"(v1.x));
        asm("mul.rn.f32x2 %0, %1, %2;" : "=l"(s3[p]) : "l"(v1.y), "l"(v1.y));
    }

    const unsigned long long HALF2 = 0x3F0000003F000000ULL;  // {0.5f, 0.5f}
    // out as u64 (2 px/elem): thread's 8 px start at 4*t; band stride NPIX/2.
    unsigned long long* obase = (unsigned long long*)out + 4 * (size_t)t;

    // Warp-uniform constant pointer for {e,e,-e^2,-e^2} pairs.
    const ulonglong2* __restrict__ cp = (const ulonglong2*)cE;

#pragma unroll 1
    for (int b = 0; b < NB; b++) {
        unsigned long long L0 = 0ULL, Q0 = 0ULL;  // Q accumulates -Q
        unsigned long long L1 = 0ULL, Q1 = 0ULL;
        unsigned long long L2 = 0ULL, Q2 = 0ULL;
        unsigned long long L3 = 0ULL, Q3 = 0ULL;
#pragma unroll
        for (int p = 0; p < NP; p++) {
            // uniform-address constant load: {e,e} and {-e^2,-e^2}
            const ulonglong2 u = cp[b * NP + p];
            const unsigned long long ee  = u.x;
            const unsigned long long ne2 = u.y;
            asm("fma.rn.f32x2 %0, %1, %2, %3;" : "=l"(L0) : "l"(a0[p]), "l"(ee),  "l"(L0));
            asm("fma.rn.f32x2 %0, %1, %2, %3;" : "=l"(Q0) : "l"(s0[p]), "l"(ne2), "l"(Q0));
            asm("fma.rn.f32x2 %0, %1, %2, %3;" : "=l"(L1) : "l"(a1[p]), "l"(ee),  "l"(L1));
            asm("fma.rn.f32x2 %0, %1, %2, %3;" : "=l"(Q1) : "l"(s1[p]), "l"(ne2), "l"(Q1));
            asm("fma.rn.f32x2 %0, %1, %2, %3;" : "=l"(L2) : "l"(a2[p]), "l"(ee),  "l"(L2));
            asm("fma.rn.f32x2 %0, %1, %2, %3;" : "=l"(Q2) : "l"(s2[p]), "l"(ne2), "l"(Q2));
            asm("fma.rn.f32x2 %0, %1, %2, %3;" : "=l"(L3) : "l"(a3[p]), "l"(ee),  "l"(L3));
            asm("fma.rn.f32x2 %0, %1, %2, %3;" : "=l"(Q3) : "l"(s3[p]), "l"(ne2), "l"(Q3));
        }
        // res = L + 0.5*(L*L - Q)
        unsigned long long n0, n1, n2, n3, r0, r1, r2, r3;
        asm("fma.rn.f32x2 %0, %1, %1, %2;" : "=l"(n0) : "l"(L0), "l"(Q0));
        asm("fma.rn.f32x2 %0, %1, %1, %2;" : "=l"(n1) : "l"(L1), "l"(Q1));
        asm("fma.rn.f32x2 %0, %1, %1, %2;" : "=l"(n2) : "l"(L2), "l"(Q2));
        asm("fma.rn.f32x2 %0, %1, %1, %2;" : "=l"(n3) : "l"(L3), "l"(Q3));
        asm("fma.rn.f32x2 %0, %1, %2, %3;" : "=l"(r0) : "l"(n0), "l"(HALF2), "l"(L0));
        asm("fma.rn.f32x2 %0, %1, %2, %3;" : "=l"(r1) : "l"(n1), "l"(HALF2), "l"(L1));
        asm("fma.rn.f32x2 %0, %1, %2, %3;" : "=l"(r2) : "l"(n2), "l"(HALF2), "l"(L2));
        asm("fma.rn.f32x2 %0, %1, %2, %3;" : "=l"(r3) : "l"(n3), "l"(HALF2), "l"(L3));

        unsigned long long* ob = obase + (size_t)b * (NPIX / 2);
        asm volatile("st.global.cs.v2.u64 [%0], {%1, %2};"
                     :: "l"(ob), "l"(r0), "l"(r1) : "memory");
        asm volatile("st.global.cs.v2.u64 [%0], {%1, %2};"
                     :: "l"(ob + 2), "l"(r2), "l"(r3) : "memory");
    }
}

extern "C" void kernel_launch(void* const* d_in, const int* in_sizes, int n_in,
                              void* d_out, int out_size)
{
    const float* E = (const float*)d_in[0];
    const float* A = (const float*)d_in[1];
    if (in_sizes[0] > in_sizes[1]) {
        E = (const float*)d_in[1];
        A = (const float*)d_in[0];
    }
    float* out = (float*)d_out;

    // 1) build {e,e,-e^2,-e^2} table in a __device__ staging buffer
    prep_kernel<<<(NB * NP + 127) / 128, 128>>>(E);

    // 2) copy staging -> constant bank (D2D async memcpy: capture-legal)
    void* cE_addr = nullptr;
    void* tbl_addr = nullptr;
    cudaGetSymbolAddress(&cE_addr, cE);
    cudaGetSymbolAddress(&tbl_addr, g_tbl);
    cudaMemcpyAsync(cE_addr, tbl_addr, sizeof(float4) * NB * NP,
                    cudaMemcpyDeviceToDevice, 0);

    // 3) main kernel
    const int threads = 128;
    const int blocks = (NPIX / 8) / threads;  // 256
    fm_mix_kernel<<<blocks, threads>>>(A, out);
}

// round 8
// speedup vs baseline: 1.3515x; 1.3515x over previous
#include <cuda_runtime.h>
#include <cuda_bf16.h>
#include <cstdint>

// Fan-model nonlinear mixing via mma.sync bf16 (HMMA, compute_103-safe):
//   out[b,x] = L + (L^2 - Q)/2,  L = sum_p E[b,p] a[p,x],  Q = sum_p E^2 a^2
// bf16 hi/lo split, K stacked (al*el dropped, ~2^-18):
//   L: ah*eh + al*eh + ah*el     Q: sh*fh + sl*fh + sh*fl   (s=a^2, f=e^2)
// mma.m16n8k16: M=16 pixels, N=8 bands, K=16 (12 used + 4 zero pad).
// CTA: 256 thr = 8 warps x 16 px = 128 px, all 224 bands (28 octets).

#define NPIX (512 * 512)
#define NP   12
#define NB   224
#define ROWB 40                      // bf16 per E-table row (80 B, conflict-free)
#define TBL_HALF (NB * ROWB * 2)     // bytes per matrix table = 17920
#define SM_BYTES (2 * TBL_HALF)      // 35840

// prebuilt E tables: [mat e | mat f], row b: [eh(12) 0(4) el(12) 0(4) 0(8)]
__device__ __align__(16) uint16_t g_tbl[2][NB][ROWB];

static __device__ __forceinline__ uint32_t pk(float lo, float hi) {
    uint32_t r;   // {lo half = bf16(lo), hi half = bf16(hi)}
    asm("cvt.rn.bf16x2.f32 %0, %1, %2;" : "=r"(r) : "f"(hi), "f"(lo));
    return r;
}
static __device__ __forceinline__ uint16_t bfb(float x) {
    __nv_bfloat16 h = __float2bfloat16(x);
    return *reinterpret_cast<uint16_t*>(&h);
}

__global__ void prep_kernel(const float* __restrict__ E) {
    int b = blockIdx.x * blockDim.x + threadIdx.x;
    if (b >= NB) return;
    uint16_t re[ROWB], rf[ROWB];
#pragma unroll
    for (int c = 0; c < ROWB; c++) { re[c] = 0; rf[c] = 0; }
#pragma unroll
    for (int p = 0; p < NP; p++) {
        float e = E[b * NP + p];
        float f = e * e;
        float eh = __bfloat162float(__float2bfloat16(e));
        float fh = __bfloat162float(__float2bfloat16(f));
        re[p]      = bfb(e);        // eh
        re[16 + p] = bfb(e - eh);   // el
        rf[p]      = bfb(f);        // fh
        rf[16 + p] = bfb(f - fh);   // fl
    }
#pragma unroll
    for (int c = 0; c < ROWB; c++) {
        g_tbl[0][b][c] = re[c];
        g_tbl[1][b][c] = rf[c];
    }
}

#define MMA(c0,c1,c2,c3,a0,a1,a2,a3,b0,b1) \
    asm volatile("mma.sync.aligned.m16n8k16.row.col.f32.bf16.bf16.f32 " \
        "{%0,%1,%2,%3}, {%4,%5,%6,%7}, {%8,%9}, {%0,%1,%2,%3};" \
        : "+f"(c0), "+f"(c1), "+f"(c2), "+f"(c3) \
        : "r"(a0), "r"(a1), "r"(a2), "r"(a3), "r"(b0), "r"(b1))

__global__ __launch_bounds__(256) void fm_mma_kernel(
    const float* __restrict__ A, float* __restrict__ out)
{
    extern __shared__ char tbl[];    // [e-table 17920 | f-table 17920]
    {
        const uint4* src = reinterpret_cast<const uint4*>(&g_tbl[0][0][0]);
        uint4* dst = reinterpret_cast<uint4*>(tbl);
        for (int j = threadIdx.x; j < SM_BYTES / 16; j += 256) dst[j] = src[j];
    }
    __syncthreads();

    const int t = threadIdx.x & 31;
    const int w = threadIdx.x >> 5;      // warp 0..7
    const int g = t >> 2;                // group 0..7
    const int i = t & 3;                 // 0..3
    const int pxA = blockIdx.x * 128 + w * 16 + g;   // fragment row g
    const int pxB = pxA + 8;                          // fragment row g+8

    // ---- build A fragments in registers ----
    // thread's A cols: k = 2i, 2i+1 (p=2i,2i+1) and k = 2i+8, 2i+9
    // (p = 2i+8, 2i+9, valid only for i<2; else zero pad).
    const int p0 = 2 * i, p1 = 2 * i + 1;
    const int p2 = 2 * i + 8, p3 = 2 * i + 9;
    float vA0 = A[(size_t)p0 * NPIX + pxA];
    float vA1 = A[(size_t)p1 * NPIX + pxA];
    float vB0 = A[(size_t)p0 * NPIX + pxB];
    float vB1 = A[(size_t)p1 * NPIX + pxB];
    float vA2 = (i < 2) ? A[(size_t)p2 * NPIX + pxA] : 0.0f;
    float vA3 = (i < 2) ? A[(size_t)p3 * NPIX + pxA] : 0.0f;
    float vB2 = (i < 2) ? A[(size_t)p2 * NPIX + pxB] : 0.0f;
    float vB3 = (i < 2) ? A[(size_t)p3 * NPIX + pxB] : 0.0f;

#define SPLIT(v, h, l) float h = __bfloat162float(__float2bfloat16(v)); float l = (v) - h;
    SPLIT(vA0, hA0, lA0) SPLIT(vA1, hA1, lA1) SPLIT(vA2, hA2, lA2) SPLIT(vA3, hA3, lA3)
    SPLIT(vB0, hB0, lB0) SPLIT(vB1, hB1, lB1) SPLIT(vB2, hB2, lB2) SPLIT(vB3, hB3, lB3)
    float sA0 = vA0 * vA0, sA1 = vA1 * vA1, sA2 = vA2 * vA2, sA3 = vA3 * vA3;
    float sB0 = vB0 * vB0, sB1 = vB1 * vB1, sB2 = vB2 * vB2, sB3 = vB3 * vB3;
    SPLIT(sA0, hsA0, lsA0) SPLIT(sA1, hsA1, lsA1) SPLIT(sA2, hsA2, lsA2) SPLIT(sA3, hsA3, lsA3)
    SPLIT(sB0, hsB0, lsB0) SPLIT(sB1, hsB1, lsB1) SPLIT(sB2, hsB2, lsB2) SPLIT(sB3, hsB3, lsB3)

    // A frag reg order: a0={g,klo}, a1={g+8,klo}, a2={g,khi}, a3={g+8,khi}
    uint32_t aH0 = pk(vA0, vA1), aH1 = pk(vB0, vB1), aH2 = pk(vA2, vA3), aH3 = pk(vB2, vB3);
    uint32_t aL0 = pk(lA0, lA1), aL1 = pk(lB0, lB1), aL2 = pk(lA2, lA3), aL3 = pk(lB2, lB3);
    uint32_t sH0 = pk(sA0, sA1), sH1 = pk(sB0, sB1), sH2 = pk(sA2, sA3), sH3 = pk(sB2, sB3);
    uint32_t sL0 = pk(lsA0, lsA1), sL1 = pk(lsB0, lsB1), sL2 = pk(lsA2, lsA3), sL3 = pk(lsB2, lsB3);

    const char* eb = tbl;                // e-table
    const char* fb = tbl + TBL_HALF;     // f-table
    const uint32_t roff = (uint32_t)g * 80 + 4 * i;   // this thread's row slot

#pragma unroll 1
    for (int o = 0; o < NB / 8; o++) {
        const uint32_t base = (uint32_t)o * (8 * 80) + roff;
        // B frags: b0 = {B[2i][g], B[2i+1][g]}, b1 = {B[2i+8][g], B[2i+9][g]}
        uint32_t e0 = *(const uint32_t*)(eb + base);        // eh, klo
        uint32_t e1 = *(const uint32_t*)(eb + base + 16);   // eh, khi (12-15 = 0)
        uint32_t l0 = *(const uint32_t*)(eb + base + 32);   // el, klo
        uint32_t l1 = *(const uint32_t*)(eb + base + 48);   // el, khi
        uint32_t f0 = *(const uint32_t*)(fb + base);
        uint32_t f1 = *(const uint32_t*)(fb + base + 16);
        uint32_t m0 = *(const uint32_t*)(fb + base + 32);
        uint32_t m1 = *(const uint32_t*)(fb + base + 48);

        float cl0 = 0.f, cl1 = 0.f, cl2 = 0.f, cl3 = 0.f;
        float cq0 = 0.f, cq1 = 0.f, cq2 = 0.f, cq3 = 0.f;
        MMA(cl0, cl1, cl2, cl3, aH0, aH1, aH2, aH3, e0, e1);   // ah*eh
        MMA(cl0, cl1, cl2, cl3, aL0, aL1, aL2, aL3, e0, e1);   // al*eh
        MMA(cl0, cl1, cl2, cl3, aH0, aH1, aH2, aH3, l0, l1);   // ah*el
        MMA(cq0, cq1, cq2, cq3, sH0, sH1, sH2, sH3, f0, f1);   // sh*fh
        MMA(cq0, cq1, cq2, cq3, sL0, sL1, sL2, sL3, f0, f1);   // sl*fh
        MMA(cq0, cq1, cq2, cq3, sH0, sH1, sH2, sH3, m0, m1);   // sh*fl

        // res = L + 0.5*(L*L - Q); C layout: c0=(g,2i) c1=(g,2i+1)
        //                                    c2=(g+8,2i) c3=(g+8,2i+1)
        float r0 = fmaf(0.5f, fmaf(cl0, cl0, -cq0), cl0);
        float r1 = fmaf(0.5f, fmaf(cl1, cl1, -cq1), cl1);
        float r2 = fmaf(0.5f, fmaf(cl2, cl2, -cq2), cl2);
        float r3 = fmaf(0.5f, fmaf(cl3, cl3, -cq3), cl3);

        float* ob = out + (size_t)(o * 8 + 2 * i) * NPIX;
        __stcs(ob + pxA, r0);
        __stcs(ob + NPIX + pxA, r1);
        __stcs(ob + pxB, r2);
        __stcs(ob + NPIX + pxB, r3);
    }
}

extern "C" void kernel_launch(void* const* d_in, const int* in_sizes, int n_in,
                              void* d_out, int out_size)
{
    const float* E = (const float*)d_in[0];
    const float* A = (const float*)d_in[1];
    if (in_sizes[0] > in_sizes[1]) {
        E = (const float*)d_in[1];
        A = (const float*)d_in[0];
    }
    float* out = (float*)d_out;

    prep_kernel<<<2, 128>>>(E);
    fm_mma_kernel<<<NPIX / 128, 256, SM_BYTES>>>(A, out);
}